// round 4
// baseline (speedup 1.0000x reference)
#include <cuda_runtime.h>
#include <cuda_bf16.h>
#include <cstdint>

#define B_   32
#define C_   768
#define HW_  1024

// -------- device scratch (allocation-free) --------
__device__ __nv_bfloat16 g_Xn[B_ * C_ * HW_];     // normalized X, bf16
__device__ __nv_bfloat16 g_Wb[2 * C_ * C_];       // interleaved bf16 weights [cb24][64][768]

// -------- GEMM tiling: M=64 (32 channels K/V-interleaved), N=64, K-stage=64 --------
#define NSTG   12
#define NCHUNK 16
#define NGS    (NSTG * NCHUNK)

#define SMEM_A_BYTES  (64 * 768 * 2)               // 98304
#define SMEM_B_OFF    SMEM_A_BYTES
#define SLOT_BYTES    (64 * 64 * 2)                // 8192
#define SMEM_S_OFF    (SMEM_B_OFF + 2 * SLOT_BYTES) // 114688
#define SMEM_G_TOTAL  (SMEM_S_OFF + 512)           // 115200 -> 2 blocks/SM fit

// norm kernel smem: 768*64 floats cache + 1024 floats reduce
#define SMEM_N_TOTAL  (768 * 64 * 4 + 1024 * 4)    // 200704

// -------- PTX helpers --------
__device__ __forceinline__ void cp16(uint32_t dst, const void* src) {
    asm volatile("cp.async.cg.shared.global [%0], [%1], 16;\n" :: "r"(dst), "l"(src) : "memory");
}
#define CP_COMMIT() asm volatile("cp.async.commit_group;\n" ::: "memory")
#define CP_WAIT(n)  asm volatile("cp.async.wait_group %0;\n" :: "n"(n) : "memory")

// ---------------------------------------------------------------------------
// Kernel 1: fused  (a) channel RMSNorm fp32->bf16 (one-pass, smem-cached)
//                  (b) weight prep fp32->bf16 K/V-interleaved
// grid 544 x 1024 threads: blocks 0..511 norm, 512..543 wprep.
// ---------------------------------------------------------------------------
__global__ void __launch_bounds__(1024, 1)
norm_wprep_kernel(const float* __restrict__ X, const float* __restrict__ Win) {
    extern __shared__ float sm[];            // [768*64] cache + [1024] red
    const int bid = blockIdx.x;
    const int t = threadIdx.x;

    if (bid < 512) {
        float* cache = sm;
        float* red = sm + 768 * 64;
        const int b = bid >> 4;
        const int hwb = (bid & 15) * 64;
        const int hw = t & 63;
        const int qc = t >> 6;               // 0..15, 48 channels each
        const int c0 = qc * 48;

        const float* xp = X + ((size_t)b * C_ + c0) * HW_ + hwb + hw;
        float s = 0.f;
#pragma unroll 8
        for (int c = 0; c < 48; c++) {
            float v = xp[c * HW_];
            cache[(c0 + c) * 64 + hw] = v;
            s = fmaf(v, v, s);
        }
        red[t] = s;
        __syncthreads();
        float tot = 0.f;
#pragma unroll
        for (int k = 0; k < 16; k++) tot += red[k * 64 + hw];
        float inv = rsqrtf(tot * (1.0f / C_) + 1e-6f);

        __nv_bfloat16* op = g_Xn + ((size_t)b * C_ + c0) * HW_ + hwb + hw;
#pragma unroll 8
        for (int c = 0; c < 48; c++)
            op[c * HW_] = __float2bfloat16(cache[(c0 + c) * 64 + hw] * inv);
    } else {
        // weight prep: g_Wb row (cb*64 + a): g=a/16, r=a%16;
        // r<8 -> Wk[cb*32+g*8+r], else Wv[cb*32+g*8+(r-8)]
        const int base = (bid - 512) * 9216;
#pragma unroll
        for (int k = 0; k < 9; k++) {
            int i4 = base + k * 1024 + t;    // < 294912
            int row = i4 / 192;
            int kc = (i4 - row * 192) * 4;
            int cb = row >> 6, a = row & 63;
            int g = a >> 4, r = a & 15;
            int wrow = (r < 8) ? (cb * 32 + g * 8 + r)
                               : (C_ + cb * 32 + g * 8 + (r - 8));
            float4 v = *(const float4*)(Win + (size_t)wrow * C_ + kc);
            __nv_bfloat162 p0 = __floats2bfloat162_rn(v.x, v.y);
            __nv_bfloat162 p1 = __floats2bfloat162_rn(v.z, v.w);
            uint2 o;
            o.x = *(uint32_t*)&p0;
            o.y = *(uint32_t*)&p1;
            *(uint2*)(g_Wb + (size_t)row * C_ + kc) = o;
        }
    }
}

// ---------------------------------------------------------------------------
// Kernel 2: fused KV-GEMM (mma.sync) + cosine gate + output scaling.
// grid (24, 32), 256 threads = 8 warps (4 M-warps x 2 N-warps), occupancy 2.
// A: 64x768 bf16 panel persistent in swizzled SMEM (32 channels interleaved K/V).
// B: 64K x 64N stages, 2-slot cp.async ring, one barrier per stage.
// Epilogue: block scales its own 32 channels of X into out.
// ---------------------------------------------------------------------------
__global__ void __launch_bounds__(256, 2)
attn_gemm_kernel(const float* __restrict__ X, float* __restrict__ out) {
    extern __shared__ char smem[];
    const uint32_t sb = (uint32_t)__cvta_generic_to_shared(smem);
    float* sS = (float*)(smem + SMEM_S_OFF);       // [32][3]
    float* sGate = sS + 96;                        // [32]

    const int tid = threadIdx.x;
    const int b = blockIdx.y;
    const int cb = blockIdx.x;

    if (tid < 96) sS[tid] = 0.f;

    // ---- A panel: 6144 x 16B, XOR-swizzled ----
    const __nv_bfloat16* wsrc = g_Wb + (size_t)cb * 64 * C_;
    for (int unit = tid; unit < 6144; unit += 256) {
        int row = unit / 96, c16 = unit - (unit / 96) * 96;
        uint32_t dst = sb + (uint32_t)(row * 1536 +
            (((c16 & 7) ^ (row & 7)) << 4) + ((c16 >> 3) << 7));
        cp16(dst, wsrc + (size_t)row * C_ + c16 * 8);
    }
    CP_COMMIT();

    const __nv_bfloat16* XnB = g_Xn + (size_t)b * C_ * HW_;
    const int warp = tid >> 5, lane = tid & 31;
    const int wm = warp >> 1, wn = warp & 1;

    const int l_krow = tid >> 3;            // 0..31 (two iters -> 0..63)
    const int l_n16  = tid & 7;

#define LOAD_B(gs_)                                                            \
    {                                                                          \
        int ch_ = (gs_) / NSTG, st_ = (gs_) - ch_ * NSTG, buf_ = (gs_) & 1;    \
        const __nv_bfloat16* src_ = XnB + (size_t)(st_ * 64) * HW_ + ch_ * 64; \
        _Pragma("unroll")                                                      \
        for (int i_ = 0; i_ < 2; i_++) {                                       \
            int kr_ = l_krow + i_ * 32;                                        \
            cp16(sb + SMEM_B_OFF + buf_ * SLOT_BYTES + kr_ * 128 +             \
                     ((l_n16 ^ (kr_ & 7)) << 4),                               \
                 src_ + (size_t)kr_ * HW_ + l_n16 * 8);                        \
        }                                                                      \
        CP_COMMIT();                                                           \
    }

    LOAD_B(0);

    float skv = 0.f, skk = 0.f, svv = 0.f;
    float acc[4][4];

#pragma unroll 1
    for (int gs = 0; gs < NGS; gs++) {
        const int st = gs % NSTG;

        CP_WAIT(0);
        __syncthreads();
        if (gs + 1 < NGS) LOAD_B(gs + 1);

        if (st == 0) {
#pragma unroll
            for (int ni = 0; ni < 4; ni++)
#pragma unroll
                for (int q = 0; q < 4; q++) acc[ni][q] = 0.f;
        }

        const uint32_t sBb = sb + SMEM_B_OFF + (gs & 1) * SLOT_BYTES;
#pragma unroll
        for (int kk = 0; kk < 4; kk++) {
            uint32_t af[4];
            {
                int row = wm * 16 + (lane & 15);
                int c16 = st * 8 + kk * 2 + (lane >> 4);
                uint32_t addr = sb + (uint32_t)(row * 1536 +
                    (((c16 & 7) ^ (row & 7)) << 4) + ((c16 >> 3) << 7));
                asm volatile(
                    "ldmatrix.sync.aligned.m8n8.x4.shared.b16 {%0,%1,%2,%3}, [%4];"
                    : "=r"(af[0]), "=r"(af[1]), "=r"(af[2]), "=r"(af[3])
                    : "r"(addr));
            }
            uint32_t bfr[4][2];
#pragma unroll
            for (int nj = 0; nj < 2; nj++) {
                int krow = kk * 16 + (lane & 15);
                int n16 = wn * 4 + nj * 2 + (lane >> 4);
                uint32_t addr = sBb + (uint32_t)(krow * 128 + ((n16 ^ (krow & 7)) << 4));
                uint32_t r0, r1, r2, r3;
                asm volatile(
                    "ldmatrix.sync.aligned.m8n8.x4.trans.shared.b16 {%0,%1,%2,%3}, [%4];"
                    : "=r"(r0), "=r"(r1), "=r"(r2), "=r"(r3)
                    : "r"(addr));
                bfr[nj * 2 + 0][0] = r0; bfr[nj * 2 + 0][1] = r1;
                bfr[nj * 2 + 1][0] = r2; bfr[nj * 2 + 1][1] = r3;
            }
#pragma unroll
            for (int ni = 0; ni < 4; ni++) {
                asm volatile(
                    "mma.sync.aligned.m16n8k16.row.col.f32.bf16.bf16.f32 "
                    "{%0,%1,%2,%3}, {%4,%5,%6,%7}, {%8,%9}, {%0,%1,%2,%3};"
                    : "+f"(acc[ni][0]), "+f"(acc[ni][1]),
                      "+f"(acc[ni][2]), "+f"(acc[ni][3])
                    : "r"(af[0]), "r"(af[1]), "r"(af[2]), "r"(af[3]),
                      "r"(bfr[ni][0]), "r"(bfr[ni][1]));
            }
        }

        if (st == NSTG - 1) {
            // rows 0..7 of 16-group = K(ch), rows 8..15 = V(same ch), same cols:
            // d0,d1 = K ; d2,d3 = V
#pragma unroll
            for (int ni = 0; ni < 4; ni++) {
                float k0 = acc[ni][0], k1 = acc[ni][1];
                float v0 = acc[ni][2], v1 = acc[ni][3];
                skv += k0 * v0 + k1 * v1;
                skk += k0 * k0 + k1 * k1;
                svv += v0 * v0 + v1 * v1;
            }
        }
    }
#undef LOAD_B

    // quad reduce (lanes 4q..4q+3 share channel row)
    skv += __shfl_down_sync(0xffffffffu, skv, 1);
    skv += __shfl_down_sync(0xffffffffu, skv, 2);
    skk += __shfl_down_sync(0xffffffffu, skk, 1);
    skk += __shfl_down_sync(0xffffffffu, skk, 2);
    svv += __shfl_down_sync(0xffffffffu, svv, 1);
    svv += __shfl_down_sync(0xffffffffu, svv, 2);

    if ((lane & 3) == 0) {
        int chl = wm * 8 + (lane >> 2);     // 0..31
        atomicAdd(&sS[chl * 3 + 0], skv);
        atomicAdd(&sS[chl * 3 + 1], skk);
        atomicAdd(&sS[chl * 3 + 2], svv);
    }
    __syncthreads();

    if (tid < 32) {
        float kv  = sS[tid * 3 + 0];
        float kk2 = sS[tid * 3 + 1];
        float vv2 = sS[tid * 3 + 2];
        float cosv = kv / ((sqrtf(kk2) + 1e-12f) * (sqrtf(vv2) + 1e-12f));
        sGate[tid] = 0.5f * cosv + 0.5f;
    }
    __syncthreads();

    // fused output scaling: this block's 32 channels x 1024 hw
    const float4* X4 = (const float4*)X;
    float4* O4 = (float4*)out;
    const size_t base4 = ((size_t)b * C_ + cb * 32) * (HW_ / 4);
#pragma unroll 4
    for (int i = tid; i < 32 * 256; i += 256) {
        int row = i >> 8;
        float a = sGate[row];
        float4 x = X4[base4 + i];
        float4 o;
        o.x = a * x.x; o.y = a * x.y; o.z = a * x.z; o.w = a * x.w;
        O4[base4 + i] = o;
    }
}

// ---------------------------------------------------------------------------
extern "C" void kernel_launch(void* const* d_in, const int* in_sizes, int n_in,
                              void* d_out, int out_size) {
    const float* X = (const float*)d_in[0];
    const float* W = (const float*)d_in[1];
    float* out = (float*)d_out;

    cudaFuncSetAttribute(norm_wprep_kernel,
                         cudaFuncAttributeMaxDynamicSharedMemorySize, SMEM_N_TOTAL);
    cudaFuncSetAttribute(attn_gemm_kernel,
                         cudaFuncAttributeMaxDynamicSharedMemorySize, SMEM_G_TOTAL);

    norm_wprep_kernel<<<544, 1024, SMEM_N_TOTAL>>>(X, W);
    attn_gemm_kernel<<<dim3(24, 32), 256, SMEM_G_TOTAL>>>(X, out);
}

// round 6
// speedup vs baseline: 1.1545x; 1.1545x over previous
#include <cuda_runtime.h>
#include <cuda_bf16.h>
#include <cstdint>

#define B_   32
#define C_   768
#define HW_  1024

// -------- device scratch (allocation-free) --------
__device__ __nv_bfloat16 g_Xn[B_ * C_ * HW_];     // normalized X, bf16
__device__ __nv_bfloat16 g_Wb[2 * C_ * C_];       // interleaved bf16 weights [cb12][128][768]

// -------- GEMM tiling: M=128 (64 ch K/V-interleaved), N-stage=128, K-stage=32 --------
#define NSTG   24            // K stages per n-chunk (32 K each -> 768)
#define NCHUNK 8             // hw chunks of 128 columns
#define NGS    (NSTG * NCHUNK)

#define SMEM_A_BYTES  (128 * 768 * 2)                // 196608
#define SMEM_B_OFF    SMEM_A_BYTES
#define SLOT_BYTES    (32 * 128 * 2)                 // 8192 per stage
#define SMEM_S_OFF    (SMEM_B_OFF + 3 * SLOT_BYTES)  // 221184
#define SMEM_G_TOTAL  (SMEM_S_OFF + 1024)            // 222208: [64][3] stats + [64] gate

// norm kernel smem
#define SMEM_N_TOTAL  (768 * 64 * 4 + 1024 * 4)      // 200704

// -------- PTX helpers --------
__device__ __forceinline__ void cp16(uint32_t dst, const void* src) {
    asm volatile("cp.async.cg.shared.global [%0], [%1], 16;\n" :: "r"(dst), "l"(src) : "memory");
}
#define CP_COMMIT() asm volatile("cp.async.commit_group;\n" ::: "memory")
#define CP_WAIT(n)  asm volatile("cp.async.wait_group %0;\n" :: "n"(n) : "memory")

// ---------------------------------------------------------------------------
// Kernel 1: fused one-pass RMSNorm (blocks 0..511) + weight prep (512..543)
// ---------------------------------------------------------------------------
__global__ void __launch_bounds__(1024, 1)
norm_wprep_kernel(const float* __restrict__ X, const float* __restrict__ Win) {
    extern __shared__ float sm[];
    const int bid = blockIdx.x;
    const int t = threadIdx.x;

    if (bid < 512) {
        float* cache = sm;
        float* red = sm + 768 * 64;
        const int b = bid >> 4;
        const int hwb = (bid & 15) * 64;
        const int hw = t & 63;
        const int qc = t >> 6;
        const int c0 = qc * 48;

        const float* xp = X + ((size_t)b * C_ + c0) * HW_ + hwb + hw;
        float s = 0.f;
#pragma unroll 8
        for (int c = 0; c < 48; c++) {
            float v = xp[c * HW_];
            cache[(c0 + c) * 64 + hw] = v;
            s = fmaf(v, v, s);
        }
        red[t] = s;
        __syncthreads();
        float tot = 0.f;
#pragma unroll
        for (int k = 0; k < 16; k++) tot += red[k * 64 + hw];
        float inv = rsqrtf(tot * (1.0f / C_) + 1e-6f);

        __nv_bfloat16* op = g_Xn + ((size_t)b * C_ + c0) * HW_ + hwb + hw;
#pragma unroll 8
        for (int c = 0; c < 48; c++)
            op[c * HW_] = __float2bfloat16(cache[(c0 + c) * 64 + hw] * inv);
    } else {
        // g_Wb row (cb*128 + a): g=a/16, r=a%16;
        // r<8 -> Wk[cb*64+g*8+r], else Wv[cb*64+g*8+(r-8)]
        const int base = (bid - 512) * 9216;
#pragma unroll
        for (int k = 0; k < 9; k++) {
            int i4 = base + k * 1024 + t;
            int row = i4 / 192;
            int kc = (i4 - row * 192) * 4;
            int cb = row >> 7, a = row & 127;
            int g = a >> 4, r = a & 15;
            int wrow = (r < 8) ? (cb * 64 + g * 8 + r)
                               : (C_ + cb * 64 + g * 8 + (r - 8));
            float4 v = *(const float4*)(Win + (size_t)wrow * C_ + kc);
            __nv_bfloat162 p0 = __floats2bfloat162_rn(v.x, v.y);
            __nv_bfloat162 p1 = __floats2bfloat162_rn(v.z, v.w);
            uint2 o;
            o.x = *(uint32_t*)&p0;
            o.y = *(uint32_t*)&p1;
            *(uint2*)(g_Wb + (size_t)row * C_ + kc) = o;
        }
    }
}

// ---------------------------------------------------------------------------
// Kernel 2: fused KV-GEMM (mma.sync) + cosine gate + output scaling.
// grid (12, 32), 256 threads = 8 warps (4 M-warps x 2 N-warps).
// B: 32K x 128N stages, 3-slot cp.async ring, loads issued 2 stages ahead.
// ---------------------------------------------------------------------------
__global__ void __launch_bounds__(256, 1)
attn_gemm_kernel(const float* __restrict__ X, float* __restrict__ out) {
    extern __shared__ char smem[];
    const uint32_t sb = (uint32_t)__cvta_generic_to_shared(smem);
    float* sS = (float*)(smem + SMEM_S_OFF);       // [64][3] = 768 B
    float* sGate = sS + 192;                       // [64]    = 256 B

    const int tid = threadIdx.x;
    const int b = blockIdx.y;
    const int cb = blockIdx.x;

    if (tid < 192) sS[tid] = 0.f;

    // ---- A panel: XOR-swizzled ----
    const __nv_bfloat16* wsrc = g_Wb + (size_t)cb * 128 * C_;
    for (int unit = tid; unit < 12288; unit += 256) {
        int row = unit / 96, c16 = unit - (unit / 96) * 96;
        uint32_t dst = sb + (uint32_t)(row * 1536 +
            (((c16 & 7) ^ (row & 7)) << 4) + ((c16 >> 3) << 7));
        cp16(dst, wsrc + (size_t)row * C_ + c16 * 8);
    }
    CP_COMMIT();

    const __nv_bfloat16* XnB = g_Xn + (size_t)b * C_ * HW_;
    const int warp = tid >> 5, lane = tid & 31;
    const int wm = warp >> 1, wn = warp & 1;

    const int l_kr = tid >> 3;     // 0..31
    const int l_u  = tid & 7;      // 16B units u and u+8

#define LOAD_B(gs_)                                                            \
    {                                                                          \
        int ch_ = (gs_) / NSTG, st_ = (gs_) - ch_ * NSTG, buf_ = (gs_) % 3;    \
        const __nv_bfloat16* src_ =                                            \
            XnB + (size_t)(st_ * 32 + l_kr) * HW_ + ch_ * 128 + l_u * 8;       \
        uint32_t dst_ = sb + SMEM_B_OFF + buf_ * SLOT_BYTES + l_kr * 256 +     \
                        (((l_u ^ l_kr) & 7) << 4);                             \
        cp16(dst_, src_);                                                      \
        cp16(dst_ + 128, src_ + 64);                                           \
        CP_COMMIT();                                                           \
    }

    LOAD_B(0);
    LOAD_B(1);

    float skv[2] = {0.f, 0.f}, skk[2] = {0.f, 0.f}, svv[2] = {0.f, 0.f};
    float acc[2][8][4];

#pragma unroll 1
    for (int gs = 0; gs < NGS; gs++) {
        const int st = gs % NSTG;

        if (gs < NGS - 1) { CP_WAIT(1); } else { CP_WAIT(0); }
        __syncthreads();
        if (gs + 2 < NGS) LOAD_B(gs + 2);

        if (st == 0) {
#pragma unroll
            for (int mi = 0; mi < 2; mi++)
#pragma unroll
                for (int ni = 0; ni < 8; ni++)
#pragma unroll
                    for (int q = 0; q < 4; q++) acc[mi][ni][q] = 0.f;
        }

        const uint32_t sBb = sb + SMEM_B_OFF + (gs % 3) * SLOT_BYTES;
#pragma unroll
        for (int kk = 0; kk < 2; kk++) {
            uint32_t af[2][4];
#pragma unroll
            for (int mi = 0; mi < 2; mi++) {
                int row = wm * 32 + mi * 16 + (lane & 15);
                int c16 = st * 4 + kk * 2 + (lane >> 4);
                uint32_t addr = sb + (uint32_t)(row * 1536 +
                    (((c16 & 7) ^ (row & 7)) << 4) + ((c16 >> 3) << 7));
                asm volatile(
                    "ldmatrix.sync.aligned.m8n8.x4.shared.b16 {%0,%1,%2,%3}, [%4];"
                    : "=r"(af[mi][0]), "=r"(af[mi][1]), "=r"(af[mi][2]), "=r"(af[mi][3])
                    : "r"(addr));
            }
            uint32_t bfr[8][2];
#pragma unroll
            for (int nj = 0; nj < 4; nj++) {
                int kr = kk * 16 + (lane & 15);
                int n16 = wn * 8 + nj * 2 + (lane >> 4);
                uint32_t addr = sBb + (uint32_t)(kr * 256 +
                    (((n16 & 7) ^ (kr & 7)) << 4) + ((n16 >> 3) << 7));
                uint32_t r0, r1, r2, r3;
                asm volatile(
                    "ldmatrix.sync.aligned.m8n8.x4.trans.shared.b16 {%0,%1,%2,%3}, [%4];"
                    : "=r"(r0), "=r"(r1), "=r"(r2), "=r"(r3)
                    : "r"(addr));
                bfr[nj * 2 + 0][0] = r0; bfr[nj * 2 + 0][1] = r1;
                bfr[nj * 2 + 1][0] = r2; bfr[nj * 2 + 1][1] = r3;
            }
#pragma unroll
            for (int mi = 0; mi < 2; mi++)
#pragma unroll
                for (int ni = 0; ni < 8; ni++) {
                    asm volatile(
                        "mma.sync.aligned.m16n8k16.row.col.f32.bf16.bf16.f32 "
                        "{%0,%1,%2,%3}, {%4,%5,%6,%7}, {%8,%9}, {%0,%1,%2,%3};"
                        : "+f"(acc[mi][ni][0]), "+f"(acc[mi][ni][1]),
                          "+f"(acc[mi][ni][2]), "+f"(acc[mi][ni][3])
                        : "r"(af[mi][0]), "r"(af[mi][1]), "r"(af[mi][2]), "r"(af[mi][3]),
                          "r"(bfr[ni][0]), "r"(bfr[ni][1]));
                }
        }

        if (st == NSTG - 1) {
            // d0,d1 = K(channel), d2,d3 = V(same channel), same columns.
#pragma unroll
            for (int mi = 0; mi < 2; mi++)
#pragma unroll
                for (int ni = 0; ni < 8; ni++) {
                    float k0 = acc[mi][ni][0], k1 = acc[mi][ni][1];
                    float v0 = acc[mi][ni][2], v1 = acc[mi][ni][3];
                    skv[mi] += k0 * v0 + k1 * v1;
                    skk[mi] += k0 * k0 + k1 * k1;
                    svv[mi] += v0 * v0 + v1 * v1;
                }
        }
    }
#undef LOAD_B

    // quad reduce (lanes 4q..4q+3 share a channel row), per mi group
#pragma unroll
    for (int mi = 0; mi < 2; mi++) {
        skv[mi] += __shfl_down_sync(0xffffffffu, skv[mi], 1);
        skv[mi] += __shfl_down_sync(0xffffffffu, skv[mi], 2);
        skk[mi] += __shfl_down_sync(0xffffffffu, skk[mi], 1);
        skk[mi] += __shfl_down_sync(0xffffffffu, skk[mi], 2);
        svv[mi] += __shfl_down_sync(0xffffffffu, svv[mi], 1);
        svv[mi] += __shfl_down_sync(0xffffffffu, svv[mi], 2);
    }
    __syncthreads();
    if ((lane & 3) == 0) {
#pragma unroll
        for (int mi = 0; mi < 2; mi++) {
            int chl = (wm * 2 + mi) * 8 + (lane >> 2);
            atomicAdd(&sS[chl * 3 + 0], skv[mi]);
            atomicAdd(&sS[chl * 3 + 1], skk[mi]);
            atomicAdd(&sS[chl * 3 + 2], svv[mi]);
        }
    }
    __syncthreads();

    if (tid < 64) {
        float kv  = sS[tid * 3 + 0];
        float kk2 = sS[tid * 3 + 1];
        float vv2 = sS[tid * 3 + 2];
        float cosv = kv / ((sqrtf(kk2) + 1e-12f) * (sqrtf(vv2) + 1e-12f));
        sGate[tid] = 0.5f * cosv + 0.5f;
    }
    __syncthreads();

    // fused output scaling: this block's 64 channels x 1024 hw
    const float4* X4 = (const float4*)X;
    float4* O4 = (float4*)out;
    const size_t base4 = ((size_t)b * C_ + cb * 64) * (HW_ / 4);
#pragma unroll 4
    for (int i = tid; i < 64 * 256; i += 256) {
        int row = i >> 8;
        float a = sGate[row];
        float4 x = X4[base4 + i];
        float4 o;
        o.x = a * x.x; o.y = a * x.y; o.z = a * x.z; o.w = a * x.w;
        O4[base4 + i] = o;
    }
}

// ---------------------------------------------------------------------------
extern "C" void kernel_launch(void* const* d_in, const int* in_sizes, int n_in,
                              void* d_out, int out_size) {
    const float* X = (const float*)d_in[0];
    const float* W = (const float*)d_in[1];
    float* out = (float*)d_out;

    cudaFuncSetAttribute(norm_wprep_kernel,
                         cudaFuncAttributeMaxDynamicSharedMemorySize, SMEM_N_TOTAL);
    cudaFuncSetAttribute(attn_gemm_kernel,
                         cudaFuncAttributeMaxDynamicSharedMemorySize, SMEM_G_TOTAL);

    norm_wprep_kernel<<<544, 1024, SMEM_N_TOTAL>>>(X, W);
    attn_gemm_kernel<<<dim3(12, 32), 256, SMEM_G_TOTAL>>>(X, out);
}